// round 11
// baseline (speedup 1.0000x reference)
#include <cuda_runtime.h>
#include <float.h>
#include <stdint.h>

#define NB 32
#define NC 80
#define HH 128
#define WW 128
#define HWSZ 16384
#define KTOP 100
#define SCORE_THRESH 0.3f
#define NMS_THRESH 0.3f
#define MAXCAND 256

// scratch (device globals: allocation-free)
__device__ float g_conf[NB * HWSZ];          // thresholded scores
__device__ unsigned char g_cls[NB * HWSZ];   // argmax channel

__device__ __forceinline__ float4 neg4() {
    return make_float4(-FLT_MAX, -FLT_MAX, -FLT_MAX, -FLT_MAX);
}
__device__ __forceinline__ float4 vmax4(float4 a, float4 b) {
    return make_float4(fmaxf(a.x, b.x), fmaxf(a.y, b.y),
                       fmaxf(a.z, b.z), fmaxf(a.w, b.w));
}

// ---------------------------------------------------------------------------
// Kernel A: 3x3 peak-NMS + channel max/argmax.
// Warp owns 4 output rows x 128 cols (4 cols/lane, float4); loads 6 rows per
// channel (halo factor 1.5 instead of 2.0 -> less L2 traffic, the binder).
// 1-deep software pipeline: next channel's 6 rows are issued before the
// current channel's compute.
// ---------------------------------------------------------------------------
__global__ void __launch_bounds__(256) peak_kernel(const float* __restrict__ hm) {
    const int b    = blockIdx.y;
    const int warp = threadIdx.x >> 5;
    const int lane = threadIdx.x & 31;
    const int y0   = (blockIdx.x << 5) + (warp << 2);   // output rows y0..y0+3
    const int x0   = lane << 2;

    const float* __restrict__ base = hm + (size_t)b * NC * HWSZ + x0;
    const bool topOK = (y0 > 0);
    const bool botOK = (y0 + 4 < HH);

    float best[16];
    int   bc[16];
#pragma unroll
    for (int i = 0; i < 16; ++i) { best[i] = 0.f; bc[i] = 0; }

    float4 A[6], B[6];

#define LOADCH(BUF, cch)                                                   \
    { const float* p_ = base + (size_t)(cch) * HWSZ;                       \
      BUF[0] = topOK ? *(const float4*)(p_ + (y0 - 1) * WW) : neg4();      \
      BUF[1] = *(const float4*)(p_ + (y0 + 0) * WW);                       \
      BUF[2] = *(const float4*)(p_ + (y0 + 1) * WW);                       \
      BUF[3] = *(const float4*)(p_ + (y0 + 2) * WW);                       \
      BUF[4] = *(const float4*)(p_ + (y0 + 3) * WW);                       \
      BUF[5] = botOK ? *(const float4*)(p_ + (y0 + 4) * WW) : neg4(); }

#define HROW(VM, CEN, K0, cch)                                                        \
    { float l_ = __shfl_up_sync(0xffffffffu, VM.w, 1);                                \
      float r_ = __shfl_down_sync(0xffffffffu, VM.x, 1);                              \
      if (lane == 0)  l_ = -FLT_MAX;                                                  \
      if (lane == 31) r_ = -FLT_MAX;                                                  \
      float q01 = fmaxf(VM.x, VM.y), q12 = fmaxf(VM.y, VM.z), q23 = fmaxf(VM.z, VM.w);\
      float h0 = fmaxf(l_, q01),  h1 = fmaxf(q01, VM.z);                              \
      float h2 = fmaxf(q12, VM.w), h3 = fmaxf(q23, r_);                               \
      if (CEN.x == h0 && CEN.x > best[K0+0]) { best[K0+0] = CEN.x; bc[K0+0] = (cch); }\
      if (CEN.y == h1 && CEN.y > best[K0+1]) { best[K0+1] = CEN.y; bc[K0+1] = (cch); }\
      if (CEN.z == h2 && CEN.z > best[K0+2]) { best[K0+2] = CEN.z; bc[K0+2] = (cch); }\
      if (CEN.w == h3 && CEN.w > best[K0+3]) { best[K0+3] = CEN.w; bc[K0+3] = (cch); } }

#define COMPUTE(BUF, cch)                                                  \
    { float4 p01 = vmax4(BUF[0], BUF[1]);                                  \
      float4 p12 = vmax4(BUF[1], BUF[2]);                                  \
      float4 p23 = vmax4(BUF[2], BUF[3]);                                  \
      float4 p34 = vmax4(BUF[3], BUF[4]);                                  \
      float4 vm0 = vmax4(p01, BUF[2]);                                     \
      float4 vm1 = vmax4(p12, BUF[3]);                                     \
      float4 vm2 = vmax4(p23, BUF[4]);                                     \
      float4 vm3 = vmax4(p34, BUF[5]);                                     \
      HROW(vm0, BUF[1], 0,  cch)                                           \
      HROW(vm1, BUF[2], 4,  cch)                                           \
      HROW(vm2, BUF[3], 8,  cch)                                           \
      HROW(vm3, BUF[4], 12, cch) }

    LOADCH(A, 0)
#pragma unroll 1
    for (int c = 0; c < NC - 2; c += 2) {     // c = 0..76
        LOADCH(B, c + 1)  COMPUTE(A, c)
        LOADCH(A, c + 2)  COMPUTE(B, c + 1)
    }
    LOADCH(B, NC - 1)
    COMPUTE(A, NC - 2)
    COMPUTE(B, NC - 1)
#undef LOADCH
#undef HROW
#undef COMPUTE

#pragma unroll
    for (int r = 0; r < 4; ++r) {
        const int o = (b << 14) + (y0 + r) * WW + x0;
        float4 s;
        s.x = best[r*4+0] > SCORE_THRESH ? best[r*4+0] : 0.f;
        s.y = best[r*4+1] > SCORE_THRESH ? best[r*4+1] : 0.f;
        s.z = best[r*4+2] > SCORE_THRESH ? best[r*4+2] : 0.f;
        s.w = best[r*4+3] > SCORE_THRESH ? best[r*4+3] : 0.f;
        *(float4*)(g_conf + o) = s;
        *(uchar4*)(g_cls + o) = make_uchar4((unsigned char)bc[r*4+0],
                                            (unsigned char)bc[r*4+1],
                                            (unsigned char)bc[r*4+2],
                                            (unsigned char)bc[r*4+3]);
    }
}

// ---------------------------------------------------------------------------
// Kernel B: per-batch top-100. Early-stop ballot-count bisection (stop once
// count in [KTOP, MAXCAND] -- the sort makes the order exact), multi-warp
// bitonic sort (256 elems, 1/thread, shfl within warp + 6 smem steps),
// gather, bitmask greedy per-class NMS, decode.
// ---------------------------------------------------------------------------
__global__ void __launch_bounds__(512) select_kernel(const float* __restrict__ wh,
                                                     const float* __restrict__ off,
                                                     float* __restrict__ out) {
    const int b = blockIdx.x;
    const int tid = threadIdx.x;
    const int wid = tid >> 5;
    const int lane = tid & 31;

    __shared__ int s_wcnt[2][16];
    __shared__ unsigned long long s_cand[MAXCAND];
    __shared__ float s_x1[KTOP], s_y1[KTOP], s_x2[KTOP], s_y2[KTOP];
    __shared__ float s_area[KTOP], s_score[KTOP];
    __shared__ int s_cls[KTOP];
    __shared__ uint4 s_sup[KTOP];
    __shared__ unsigned int s_alive[4];
    __shared__ int s_n;

    // ---- load 32 score keys per thread into registers (coalesced) ----
    const float* cf = g_conf + (size_t)b * HWSZ;
    unsigned int key[32];
#pragma unroll
    for (int i = 0; i < 32; ++i)
        key[i] = __float_as_uint(cf[i * 512 + tid]);   // idx = i*512 + tid

    // ---- threshold by bisection with EARLY STOP: any T with
    // count(T) in [KTOP, MAXCAND] is good enough (sort finishes the job).
    // Invariant: count(lo) >= KTOP > count(hi). Keys in {0} U (0.3, 1.0).
    unsigned int lo = 1u, hi = 0x3F800000u;            // 1.0f strict upper bound
    unsigned int probe = 0x3F7F0000u;                  // seed ~0.99609
    unsigned int thr;
    int par = 0;
    while (true) {
        int c = 0;
#pragma unroll
        for (int i = 0; i < 32; ++i) c += (key[i] >= probe);
        c = __reduce_add_sync(0xffffffffu, c);
        if (lane == 0) s_wcnt[par][wid] = c;
        __syncthreads();
        int cnt = 0;
#pragma unroll
        for (int w = 0; w < 16; ++w) cnt += s_wcnt[par][w];
        par ^= 1;
        if (cnt >= KTOP && cnt <= MAXCAND) { thr = probe; break; }
        if (cnt >= KTOP) lo = probe; else hi = probe;
        if (hi - lo <= 1u) { thr = lo; break; }
        probe = lo + ((hi - lo) >> 1);
    }

    // ---- compact candidates key >= thr, packed (key<<32)|~idx ----
    if (tid == 0) s_n = 0;
    __syncthreads();
#pragma unroll
    for (int i = 0; i < 32; ++i) {
        if (key[i] >= thr) {                 // thr >= 1 excludes zeros
            int p = atomicAdd(&s_n, 1);
            if (p < MAXCAND) {
                unsigned int idx = (unsigned int)(i * 512 + tid);
                s_cand[p] = ((unsigned long long)key[i] << 32) | (unsigned int)(~idx);
            }
        }
    }
    __syncthreads();
    int n = s_n < MAXCAND ? s_n : MAXCAND;
    for (int p = n + tid; p < MAXCAND; p += 512) s_cand[p] = 0ULL;
    __syncthreads();

    // ---- bitonic sort of 256 u64 descending; 1 element/thread across 8
    // warps: shfl_xor for j<32 (warps run in parallel), smem for j>=32.
    {
        unsigned long long v = (tid < MAXCAND) ? s_cand[tid] : 0ULL;
#pragma unroll
        for (int k = 2; k <= 256; k <<= 1) {
#pragma unroll
            for (int j = k >> 1; j > 0; j >>= 1) {
                bool desc = ((tid & k) == 0);
                bool low  = ((tid & j) == 0);
                bool keepMax = (desc == low);
                unsigned long long pv;
                if (j >= 32) {
                    __syncthreads();
                    if (tid < MAXCAND) s_cand[tid] = v;
                    __syncthreads();
                    pv = (tid < MAXCAND) ? s_cand[tid ^ j] : 0ULL;
                } else {
                    pv = __shfl_xor_sync(0xffffffffu, v, j);
                }
                unsigned long long mx = v > pv ? v : pv;
                unsigned long long mn = v > pv ? pv : v;
                v = keepMax ? mx : mn;
            }
        }
        __syncthreads();
        if (tid < MAXCAND) s_cand[tid] = v;
    }
    if (tid < 4) s_alive[tid] = 0u;
    if (tid < KTOP) s_sup[tid] = make_uint4(0u, 0u, 0u, 0u);
    __syncthreads();

    // ---- gather top-100, decode boxes (mirrors reference FP op order) ----
    if (tid < KTOP) {
        unsigned long long pk = s_cand[tid];
        unsigned int kk = (unsigned int)(pk >> 32);
        float score = __uint_as_float(kk);
        bool valid = score > SCORE_THRESH;
        float x1 = 0.f, y1 = 0.f, x2 = 0.f, y2 = 0.f;
        int cl = 0;
        if (valid) {
            unsigned int idx = ~((unsigned int)(pk & 0xffffffffu));
            int xi = idx & (WW - 1);
            int yi = idx >> 7;
            const float* whb = wh  + (size_t)b * 2 * HWSZ;
            const float* ofb = off + (size_t)b * 2 * HWSZ;
            float bw = whb[idx];
            float bh = whb[HWSZ + idx];
            float o0 = ofb[idx];
            float o1 = ofb[HWSZ + idx];
            float cx = (float)xi + o0;
            float cy = (float)yi + o1;
            const float invW = 1.0f / (float)WW;   // exact power of two
            const float invH = 1.0f / (float)HH;
            x1 = (cx - bw * 0.5f) * invW;
            y1 = (cy - bh * 0.5f) * invH;
            x2 = (cx + bw * 0.5f) * invW;
            y2 = (cy + bh * 0.5f) * invH;
            cl = (int)g_cls[(size_t)b * HWSZ + idx];
            atomicOr(&s_alive[tid >> 5], 1u << (tid & 31));
        }
        s_x1[tid] = x1; s_y1[tid] = y1; s_x2[tid] = x2; s_y2[tid] = y2;
        s_area[tid] = (x2 - x1) * (y2 - y1);
        s_score[tid] = score;
        s_cls[tid] = cl;
    }
    __syncthreads();

    // ---- parallel suppression-matrix build (bitmask rows) ----
    for (int idx = tid; idx < KTOP * KTOP; idx += 512) {
        int i = idx / KTOP;
        int jj = idx - i * KTOP;
        if (jj > i && s_cls[i] == s_cls[jj]) {
            float lx = fmaxf(s_x1[i], s_x1[jj]);
            float ly = fmaxf(s_y1[i], s_y1[jj]);
            float rx = fminf(s_x2[i], s_x2[jj]);
            float ry = fminf(s_y2[i], s_y2[jj]);
            float iw = fmaxf(rx - lx, 0.f);
            float ih = fmaxf(ry - ly, 0.f);
            float inter = iw * ih;
            float iou = inter / (s_area[i] + s_area[jj] - inter + 1e-9f);
            if (iou > NMS_THRESH)
                atomicOr(&((unsigned int*)s_sup)[i * 4 + (jj >> 5)], 1u << (jj & 31));
        }
    }
    __syncthreads();

    // ---- serial greedy sweep over bitmasks (thread 0, row prefetch) ----
    if (tid == 0) {
        unsigned int a0 = s_alive[0], a1 = s_alive[1], a2 = s_alive[2], a3 = s_alive[3];
        uint4 row = s_sup[0];
        for (int i = 0; i < KTOP; ++i) {
            uint4 nxt = (i + 1 < KTOP) ? s_sup[i + 1] : make_uint4(0u, 0u, 0u, 0u);
            unsigned int aw = (i < 32) ? a0 : (i < 64) ? a1 : (i < 96) ? a2 : a3;
            if ((aw >> (i & 31)) & 1u) {
                a0 &= ~row.x; a1 &= ~row.y; a2 &= ~row.z; a3 &= ~row.w;
            }
            row = nxt;
        }
        s_alive[0] = a0; s_alive[1] = a1; s_alive[2] = a2; s_alive[3] = a3;
    }
    __syncthreads();

    // ---- write dets (scale to image via the reference's recompute path) ----
    if (tid < KTOP) {
        bool alive = (s_alive[tid >> 5] >> (tid & 31)) & 1u;
        float* o = out + ((size_t)b * KTOP + tid) * 6;
        if (alive) {
            float x1 = s_x1[tid], y1 = s_y1[tid], x2 = s_x2[tid], y2 = s_y2[tid];
            float cxm = (x1 + x2) * 0.5f;
            float cym = (y1 + y2) * 0.5f;
            float cw = x2 - x1;
            float ch = y2 - y1;
            o[0] = (cxm - cw * 0.5f) * 512.f;
            o[1] = (cym - ch * 0.5f) * 512.f;
            o[2] = (cxm + cw * 0.5f) * 512.f;
            o[3] = (cym + ch * 0.5f) * 512.f;
            o[4] = s_score[tid];
            o[5] = (float)s_cls[tid];
        } else {
            o[0] = 0.f; o[1] = 0.f; o[2] = 0.f;
            o[3] = 0.f; o[4] = 0.f; o[5] = 0.f;
        }
    }
}

extern "C" void kernel_launch(void* const* d_in, const int* in_sizes, int n_in,
                              void* d_out, int out_size) {
    const float* hm  = (const float*)d_in[0];
    const float* wh  = (const float*)d_in[1];
    const float* off = (const float*)d_in[2];
    float* out = (float*)d_out;

    dim3 gA(HH / 32, NB);     // 4 x 32 = 128 blocks
    peak_kernel<<<gA, 256>>>(hm);
    select_kernel<<<NB, 512>>>(wh, off, out);
}

// round 12
// speedup vs baseline: 1.1272x; 1.1272x over previous
#include <cuda_runtime.h>
#include <float.h>
#include <stdint.h>

#define NB 32
#define NC 80
#define HH 128
#define WW 128
#define HWSZ 16384
#define KTOP 100
#define SCORE_THRESH 0.3f
#define NMS_THRESH 0.3f
#define MAXCAND 256

// scratch (device globals: allocation-free)
__device__ float g_conf[NB * HWSZ];          // thresholded scores
__device__ unsigned char g_cls[NB * HWSZ];   // argmax channel

__device__ __forceinline__ float4 neg4() {
    return make_float4(-FLT_MAX, -FLT_MAX, -FLT_MAX, -FLT_MAX);
}

// ---------------------------------------------------------------------------
// Kernel A: 3x3 peak-NMS + channel max/argmax.
// Warp owns 2 output rows x 128 cols (4 cols/lane, float4) and loads ONLY its
// own 2 rows from global; vertical halo rows are exchanged through a
// double-buffered 18-row smem tile (edge warps pipeline 1 extra global row).
// L2 read traffic: 1.125x compulsory instead of 2.0x (R10) -- R10 sat at the
// LTS cap. 3-stage rotating pipeline, one barrier per channel.
// ---------------------------------------------------------------------------
__global__ void __launch_bounds__(256, 2) peak_kernel(const float* __restrict__ hm) {
    const int b    = blockIdx.y;
    const int warp = threadIdx.x >> 5;
    const int lane = threadIdx.x & 31;
    const int y0   = (blockIdx.x << 4) + (warp << 1);   // output rows y0, y0+1
    const int x0   = lane << 2;

    const float* __restrict__ base = hm + (size_t)b * NC * HWSZ + x0;
    const bool topOK = (y0 > 0);          // meaningful for warp 0 only
    const bool botOK = (y0 + 2 < HH);     // meaningful for warp 7 only

    // [buffer][block-row -1 .. 16 mapped to 0..17][lane]
    __shared__ float4 sbuf[2][18][32];

    float best[8] = {0.f, 0.f, 0.f, 0.f, 0.f, 0.f, 0.f, 0.f};
    int   bc[8]   = {0, 0, 0, 0, 0, 0, 0, 0};

    float4 Ha, Oa1, Oa2, Hb, Ob1, Ob2, Hc, Oc1, Oc2;

#define LOADCH(H, O1, O2, cch)                                             \
    { const float* p_ = base + (size_t)(cch) * HWSZ;                       \
      O1 = *(const float4*)(p_ + (y0 + 0) * WW);                           \
      O2 = *(const float4*)(p_ + (y0 + 1) * WW);                           \
      if (warp == 0) H = topOK ? *(const float4*)(p_ + (y0 - 1) * WW) : neg4(); \
      if (warp == 7) H = botOK ? *(const float4*)(p_ + (y0 + 2) * WW) : neg4(); }

#define STORECH(H, O1, O2, cch)                                            \
    { const int bi_ = (cch) & 1;                                           \
      sbuf[bi_][(warp << 1) + 1][lane] = O1;                               \
      sbuf[bi_][(warp << 1) + 2][lane] = O2;                               \
      if (warp == 0) sbuf[bi_][0][lane]  = H;                              \
      if (warp == 7) sbuf[bi_][17][lane] = H; }

#define COMPUTE(O1, O2, cch)                                                          \
    { const int bi_ = (cch) & 1;                                                      \
      float4 v0 = sbuf[bi_][(warp << 1) + 0][lane];                                   \
      float4 v3 = sbuf[bi_][(warp << 1) + 3][lane];                                   \
      float4 t_, cma_, cmb_;                                                          \
      t_.x = fmaxf(O1.x, O2.x); t_.y = fmaxf(O1.y, O2.y);                             \
      t_.z = fmaxf(O1.z, O2.z); t_.w = fmaxf(O1.w, O2.w);                             \
      cma_.x = fmaxf(t_.x, v0.x); cma_.y = fmaxf(t_.y, v0.y);                         \
      cma_.z = fmaxf(t_.z, v0.z); cma_.w = fmaxf(t_.w, v0.w);                         \
      cmb_.x = fmaxf(t_.x, v3.x); cmb_.y = fmaxf(t_.y, v3.y);                         \
      cmb_.z = fmaxf(t_.z, v3.z); cmb_.w = fmaxf(t_.w, v3.w);                         \
      float la_ = __shfl_up_sync(0xffffffffu, cma_.w, 1);                             \
      float ra_ = __shfl_down_sync(0xffffffffu, cma_.x, 1);                           \
      float lb_ = __shfl_up_sync(0xffffffffu, cmb_.w, 1);                             \
      float rb_ = __shfl_down_sync(0xffffffffu, cmb_.x, 1);                           \
      if (lane == 0)  { la_ = -FLT_MAX; lb_ = -FLT_MAX; }                             \
      if (lane == 31) { ra_ = -FLT_MAX; rb_ = -FLT_MAX; }                             \
      float pa01 = fmaxf(cma_.x, cma_.y), pa12 = fmaxf(cma_.y, cma_.z),               \
            pa23 = fmaxf(cma_.z, cma_.w);                                             \
      float pb01 = fmaxf(cmb_.x, cmb_.y), pb12 = fmaxf(cmb_.y, cmb_.z),               \
            pb23 = fmaxf(cmb_.z, cmb_.w);                                             \
      float ha0 = fmaxf(la_, pa01),   ha1 = fmaxf(pa01, cma_.z);                      \
      float ha2 = fmaxf(pa12, cma_.w), ha3 = fmaxf(pa23, ra_);                        \
      float hb0 = fmaxf(lb_, pb01),   hb1 = fmaxf(pb01, cmb_.z);                      \
      float hb2 = fmaxf(pb12, cmb_.w), hb3 = fmaxf(pb23, rb_);                        \
      if (O1.x == ha0 && O1.x > best[0]) { best[0] = O1.x; bc[0] = (cch); }           \
      if (O1.y == ha1 && O1.y > best[1]) { best[1] = O1.y; bc[1] = (cch); }           \
      if (O1.z == ha2 && O1.z > best[2]) { best[2] = O1.z; bc[2] = (cch); }           \
      if (O1.w == ha3 && O1.w > best[3]) { best[3] = O1.w; bc[3] = (cch); }           \
      if (O2.x == hb0 && O2.x > best[4]) { best[4] = O2.x; bc[4] = (cch); }           \
      if (O2.y == hb1 && O2.y > best[5]) { best[5] = O2.y; bc[5] = (cch); }           \
      if (O2.z == hb2 && O2.z > best[6]) { best[6] = O2.z; bc[6] = (cch); }           \
      if (O2.w == hb3 && O2.w > best[7]) { best[7] = O2.w; bc[7] = (cch); } }

    LOADCH(Ha, Oa1, Oa2, 0)
    STORECH(Ha, Oa1, Oa2, 0)
    LOADCH(Hb, Ob1, Ob2, 1)
    __syncthreads();                      // buf[0] (channel 0) visible
#pragma unroll 1
    for (int c = 0; c < NC - 3; c += 3) { // 26 iters: c = 0..75, processes 0..77
        LOADCH(Hc, Oc1, Oc2, c + 2)  STORECH(Hb, Ob1, Ob2, c + 1)
        COMPUTE(Oa1, Oa2, c)         __syncthreads();
        LOADCH(Ha, Oa1, Oa2, c + 3)  STORECH(Hc, Oc1, Oc2, c + 2)
        COMPUTE(Ob1, Ob2, c + 1)     __syncthreads();
        LOADCH(Hb, Ob1, Ob2, c + 4)  STORECH(Ha, Oa1, Oa2, c + 3)
        COMPUTE(Oc1, Oc2, c + 2)     __syncthreads();
    }
    // after loop: A holds ch 78 (stored, visible), B holds ch 79 (in regs)
    STORECH(Hb, Ob1, Ob2, NC - 1)
    COMPUTE(Oa1, Oa2, NC - 2)
    __syncthreads();
    COMPUTE(Ob1, Ob2, NC - 1)
#undef LOADCH
#undef STORECH
#undef COMPUTE

    const int o0 = (b << 14) + (y0 + 0) * WW + x0;
    const int o1 = (b << 14) + (y0 + 1) * WW + x0;
    float4 s0, s1;
    s0.x = best[0] > SCORE_THRESH ? best[0] : 0.f;
    s0.y = best[1] > SCORE_THRESH ? best[1] : 0.f;
    s0.z = best[2] > SCORE_THRESH ? best[2] : 0.f;
    s0.w = best[3] > SCORE_THRESH ? best[3] : 0.f;
    s1.x = best[4] > SCORE_THRESH ? best[4] : 0.f;
    s1.y = best[5] > SCORE_THRESH ? best[5] : 0.f;
    s1.z = best[6] > SCORE_THRESH ? best[6] : 0.f;
    s1.w = best[7] > SCORE_THRESH ? best[7] : 0.f;
    *(float4*)(g_conf + o0) = s0;
    *(float4*)(g_conf + o1) = s1;
    *(uchar4*)(g_cls + o0) = make_uchar4((unsigned char)bc[0], (unsigned char)bc[1],
                                         (unsigned char)bc[2], (unsigned char)bc[3]);
    *(uchar4*)(g_cls + o1) = make_uchar4((unsigned char)bc[4], (unsigned char)bc[5],
                                         (unsigned char)bc[6], (unsigned char)bc[7]);
}

// ---------------------------------------------------------------------------
// Kernel B: per-batch top-100. Early-stop ballot-count bisection with cheap
// warp-0 count reduction (no per-thread 16-way smem sums), multi-warp bitonic
// sort, gather, bitmask greedy per-class NMS, decode.
// ---------------------------------------------------------------------------
__global__ void __launch_bounds__(512) select_kernel(const float* __restrict__ wh,
                                                     const float* __restrict__ off,
                                                     float* __restrict__ out) {
    const int b = blockIdx.x;
    const int tid = threadIdx.x;
    const int wid = tid >> 5;
    const int lane = tid & 31;

    __shared__ int s_wcnt[16];
    __shared__ int s_tot;
    __shared__ unsigned long long s_cand[MAXCAND];
    __shared__ float s_x1[KTOP], s_y1[KTOP], s_x2[KTOP], s_y2[KTOP];
    __shared__ float s_area[KTOP], s_score[KTOP];
    __shared__ int s_cls[KTOP];
    __shared__ uint4 s_sup[KTOP];
    __shared__ unsigned int s_alive[4];
    __shared__ int s_n;

    // ---- load 32 score keys per thread into registers (coalesced) ----
    const float* cf = g_conf + (size_t)b * HWSZ;
    unsigned int key[32];
#pragma unroll
    for (int i = 0; i < 32; ++i)
        key[i] = __float_as_uint(cf[i * 512 + tid]);   // idx = i*512 + tid

    // ---- threshold by bisection with EARLY STOP: any T with
    // count(T) in [KTOP, MAXCAND] is good enough (sort finishes the job).
    // Counts: warp __reduce_add -> lane0 smem -> warp0 reduce -> broadcast.
    unsigned int lo = 1u, hi = 0x3F800000u;            // 1.0f strict upper bound
    unsigned int probe = 0x3F7F0000u;                  // seed ~0.99609
    unsigned int thr;
    while (true) {
        int c = 0;
#pragma unroll
        for (int i = 0; i < 32; ++i) c += (key[i] >= probe);
        c = __reduce_add_sync(0xffffffffu, c);
        if (lane == 0) s_wcnt[wid] = c;
        __syncthreads();
        if (wid == 0) {
            int t = (lane < 16) ? s_wcnt[lane] : 0;
            t = __reduce_add_sync(0xffffffffu, t);
            if (lane == 0) s_tot = t;
        }
        __syncthreads();
        int cnt = s_tot;
        if (cnt >= KTOP && cnt <= MAXCAND) { thr = probe; break; }
        if (cnt >= KTOP) lo = probe; else hi = probe;
        if (hi - lo <= 1u) { thr = lo; break; }
        probe = lo + ((hi - lo) >> 1);
    }

    // ---- compact candidates key >= thr, packed (key<<32)|~idx ----
    if (tid == 0) s_n = 0;
    __syncthreads();
#pragma unroll
    for (int i = 0; i < 32; ++i) {
        if (key[i] >= thr) {                 // thr >= 1 excludes zeros
            int p = atomicAdd(&s_n, 1);
            if (p < MAXCAND) {
                unsigned int idx = (unsigned int)(i * 512 + tid);
                s_cand[p] = ((unsigned long long)key[i] << 32) | (unsigned int)(~idx);
            }
        }
    }
    __syncthreads();
    int n = s_n < MAXCAND ? s_n : MAXCAND;
    for (int p = n + tid; p < MAXCAND; p += 512) s_cand[p] = 0ULL;
    __syncthreads();

    // ---- bitonic sort of 256 u64 descending; 1 element/thread across 8
    // warps: shfl_xor for j<32 (warps run in parallel), smem for j>=32.
    {
        unsigned long long v = (tid < MAXCAND) ? s_cand[tid] : 0ULL;
#pragma unroll
        for (int k = 2; k <= 256; k <<= 1) {
#pragma unroll
            for (int j = k >> 1; j > 0; j >>= 1) {
                bool desc = ((tid & k) == 0);
                bool low  = ((tid & j) == 0);
                bool keepMax = (desc == low);
                unsigned long long pv;
                if (j >= 32) {
                    __syncthreads();
                    if (tid < MAXCAND) s_cand[tid] = v;
                    __syncthreads();
                    pv = (tid < MAXCAND) ? s_cand[tid ^ j] : 0ULL;
                } else {
                    pv = __shfl_xor_sync(0xffffffffu, v, j);
                }
                unsigned long long mx = v > pv ? v : pv;
                unsigned long long mn = v > pv ? pv : v;
                v = keepMax ? mx : mn;
            }
        }
        __syncthreads();
        if (tid < MAXCAND) s_cand[tid] = v;
    }
    if (tid < 4) s_alive[tid] = 0u;
    if (tid < KTOP) s_sup[tid] = make_uint4(0u, 0u, 0u, 0u);
    __syncthreads();

    // ---- gather top-100, decode boxes (mirrors reference FP op order) ----
    if (tid < KTOP) {
        unsigned long long pk = s_cand[tid];
        unsigned int kk = (unsigned int)(pk >> 32);
        float score = __uint_as_float(kk);
        bool valid = score > SCORE_THRESH;
        float x1 = 0.f, y1 = 0.f, x2 = 0.f, y2 = 0.f;
        int cl = 0;
        if (valid) {
            unsigned int idx = ~((unsigned int)(pk & 0xffffffffu));
            int xi = idx & (WW - 1);
            int yi = idx >> 7;
            const float* whb = wh  + (size_t)b * 2 * HWSZ;
            const float* ofb = off + (size_t)b * 2 * HWSZ;
            float bw = whb[idx];
            float bh = whb[HWSZ + idx];
            float o0 = ofb[idx];
            float o1 = ofb[HWSZ + idx];
            float cx = (float)xi + o0;
            float cy = (float)yi + o1;
            const float invW = 1.0f / (float)WW;   // exact power of two
            const float invH = 1.0f / (float)HH;
            x1 = (cx - bw * 0.5f) * invW;
            y1 = (cy - bh * 0.5f) * invH;
            x2 = (cx + bw * 0.5f) * invW;
            y2 = (cy + bh * 0.5f) * invH;
            cl = (int)g_cls[(size_t)b * HWSZ + idx];
            atomicOr(&s_alive[tid >> 5], 1u << (tid & 31));
        }
        s_x1[tid] = x1; s_y1[tid] = y1; s_x2[tid] = x2; s_y2[tid] = y2;
        s_area[tid] = (x2 - x1) * (y2 - y1);
        s_score[tid] = score;
        s_cls[tid] = cl;
    }
    __syncthreads();

    // ---- parallel suppression-matrix build (bitmask rows) ----
    for (int idx = tid; idx < KTOP * KTOP; idx += 512) {
        int i = idx / KTOP;
        int jj = idx - i * KTOP;
        if (jj > i && s_cls[i] == s_cls[jj]) {
            float lx = fmaxf(s_x1[i], s_x1[jj]);
            float ly = fmaxf(s_y1[i], s_y1[jj]);
            float rx = fminf(s_x2[i], s_x2[jj]);
            float ry = fminf(s_y2[i], s_y2[jj]);
            float iw = fmaxf(rx - lx, 0.f);
            float ih = fmaxf(ry - ly, 0.f);
            float inter = iw * ih;
            float iou = inter / (s_area[i] + s_area[jj] - inter + 1e-9f);
            if (iou > NMS_THRESH)
                atomicOr(&((unsigned int*)s_sup)[i * 4 + (jj >> 5)], 1u << (jj & 31));
        }
    }
    __syncthreads();

    // ---- serial greedy sweep over bitmasks (thread 0, row prefetch) ----
    if (tid == 0) {
        unsigned int a0 = s_alive[0], a1 = s_alive[1], a2 = s_alive[2], a3 = s_alive[3];
        uint4 row = s_sup[0];
        for (int i = 0; i < KTOP; ++i) {
            uint4 nxt = (i + 1 < KTOP) ? s_sup[i + 1] : make_uint4(0u, 0u, 0u, 0u);
            unsigned int aw = (i < 32) ? a0 : (i < 64) ? a1 : (i < 96) ? a2 : a3;
            if ((aw >> (i & 31)) & 1u) {
                a0 &= ~row.x; a1 &= ~row.y; a2 &= ~row.z; a3 &= ~row.w;
            }
            row = nxt;
        }
        s_alive[0] = a0; s_alive[1] = a1; s_alive[2] = a2; s_alive[3] = a3;
    }
    __syncthreads();

    // ---- write dets (scale to image via the reference's recompute path) ----
    if (tid < KTOP) {
        bool alive = (s_alive[tid >> 5] >> (tid & 31)) & 1u;
        float* o = out + ((size_t)b * KTOP + tid) * 6;
        if (alive) {
            float x1 = s_x1[tid], y1 = s_y1[tid], x2 = s_x2[tid], y2 = s_y2[tid];
            float cxm = (x1 + x2) * 0.5f;
            float cym = (y1 + y2) * 0.5f;
            float cw = x2 - x1;
            float ch = y2 - y1;
            o[0] = (cxm - cw * 0.5f) * 512.f;
            o[1] = (cym - ch * 0.5f) * 512.f;
            o[2] = (cxm + cw * 0.5f) * 512.f;
            o[3] = (cym + ch * 0.5f) * 512.f;
            o[4] = s_score[tid];
            o[5] = (float)s_cls[tid];
        } else {
            o[0] = 0.f; o[1] = 0.f; o[2] = 0.f;
            o[3] = 0.f; o[4] = 0.f; o[5] = 0.f;
        }
    }
}

extern "C" void kernel_launch(void* const* d_in, const int* in_sizes, int n_in,
                              void* d_out, int out_size) {
    const float* hm  = (const float*)d_in[0];
    const float* wh  = (const float*)d_in[1];
    const float* off = (const float*)d_in[2];
    float* out = (float*)d_out;

    dim3 gA(HH / 16, NB);     // 8 x 32 = 256 blocks
    peak_kernel<<<gA, 256>>>(hm);
    select_kernel<<<NB, 512>>>(wh, off, out);
}

// round 13
// speedup vs baseline: 1.2309x; 1.0919x over previous
#include <cuda_runtime.h>
#include <float.h>
#include <stdint.h>

#define NB 32
#define NC 80
#define HH 128
#define WW 128
#define HWSZ 16384
#define KTOP 100
#define SCORE_THRESH 0.3f
#define NMS_THRESH 0.3f
#define MAXCAND 256
#define DEPTH 5            // cp.async pipeline depth (smem ring slots)

// scratch (device globals: allocation-free)
__device__ float g_conf[NB * HWSZ];          // thresholded scores
__device__ unsigned char g_cls[NB * HWSZ];   // argmax channel

// ---------------------------------------------------------------------------
// Kernel A: 3x3 peak-NMS + channel max/argmax.
// CTA owns a 16-row stripe; per channel it cp.asyncs 18 rows (own 16 + 2
// halo; 1.125x traffic instead of R10's 2.0x which sat at the LTS cap) into
// a 5-slot smem ring. wait_group(DEPTH-1) + uniform commit-per-iteration
// keeps ~4 channels of DRAM latency in flight. Warp computes 2 output rows
// from smem; math identical to the R10 kernel.
// ---------------------------------------------------------------------------
__global__ void __launch_bounds__(256, 2) peak_kernel(const float* __restrict__ hm) {
    const int b     = blockIdx.y;
    const int tid   = threadIdx.x;
    const int warp  = tid >> 5;
    const int lane  = tid & 31;
    const int ybase = blockIdx.x << 4;          // first output row of stripe

    __shared__ float sbuf[DEPTH][18][128];      // 45 KB static

    // pre-fill out-of-image halo rows with -FLT_MAX (never cp.async'd,
    // constant across channels, so fill every slot once)
    if (blockIdx.x == 0) {
        for (int q = tid; q < DEPTH * 128; q += 256)
            sbuf[q >> 7][0][q & 127] = -FLT_MAX;
    }
    if (blockIdx.x == (HH / 16) - 1) {
        for (int q = tid; q < DEPTH * 128; q += 256)
            sbuf[q >> 7][17][q & 127] = -FLT_MAX;
    }

    const float* __restrict__ gbase = hm + (size_t)b * NC * HWSZ;

#define ISSUE(ch, slot)                                                          \
    { const float* cb_ = gbase + (size_t)(ch) * HWSZ;                            \
      for (int q_ = tid; q_ < 576; q_ += 256) {                                  \
          int srow_ = q_ >> 5;                                                   \
          int seg_  = q_ & 31;                                                   \
          int gy_ = ybase + srow_ - 1;                                           \
          if (gy_ >= 0 && gy_ < HH) {                                            \
              unsigned da_ = (unsigned)__cvta_generic_to_shared(                 \
                                  &sbuf[slot][srow_][seg_ << 2]);                \
              asm volatile("cp.async.cg.shared.global [%0], [%1], 16;"           \
                           :: "r"(da_), "l"(cb_ + gy_ * WW + (seg_ << 2)));      \
          }                                                                      \
      } }

    float best[8] = {0.f, 0.f, 0.f, 0.f, 0.f, 0.f, 0.f, 0.f};
    int   bc[8]   = {0, 0, 0, 0, 0, 0, 0, 0};

    // prologue: fill the ring
#pragma unroll
    for (int p = 0; p < DEPTH; ++p) {
        ISSUE(p, p)
        asm volatile("cp.async.commit_group;");
    }

    int slot = 0;
#pragma unroll 1
    for (int c = 0; c < NC; ++c) {
        // groups committed so far: c + DEPTH; waiting for <= DEPTH-1 pending
        // makes group c (channel c) complete. Commit below runs EVERY iter
        // (possibly empty) so this numbering holds through the tail.
        asm volatile("cp.async.wait_group %0;" :: "n"(DEPTH - 1));
        __syncthreads();

        {
            const int r0 = warp << 1;
            float4 v0 = *(const float4*)&sbuf[slot][r0 + 0][lane << 2];
            float4 v1 = *(const float4*)&sbuf[slot][r0 + 1][lane << 2];
            float4 v2 = *(const float4*)&sbuf[slot][r0 + 2][lane << 2];
            float4 v3 = *(const float4*)&sbuf[slot][r0 + 3][lane << 2];

            float4 t, cma, cmb;
            t.x = fmaxf(v1.x, v2.x); t.y = fmaxf(v1.y, v2.y);
            t.z = fmaxf(v1.z, v2.z); t.w = fmaxf(v1.w, v2.w);
            cma.x = fmaxf(t.x, v0.x); cma.y = fmaxf(t.y, v0.y);
            cma.z = fmaxf(t.z, v0.z); cma.w = fmaxf(t.w, v0.w);
            cmb.x = fmaxf(t.x, v3.x); cmb.y = fmaxf(t.y, v3.y);
            cmb.z = fmaxf(t.z, v3.z); cmb.w = fmaxf(t.w, v3.w);

            float la = __shfl_up_sync(0xffffffffu, cma.w, 1);
            float ra = __shfl_down_sync(0xffffffffu, cma.x, 1);
            float lb = __shfl_up_sync(0xffffffffu, cmb.w, 1);
            float rb = __shfl_down_sync(0xffffffffu, cmb.x, 1);
            if (lane == 0)  { la = -FLT_MAX; lb = -FLT_MAX; }
            if (lane == 31) { ra = -FLT_MAX; rb = -FLT_MAX; }

            float pa01 = fmaxf(cma.x, cma.y), pa12 = fmaxf(cma.y, cma.z),
                  pa23 = fmaxf(cma.z, cma.w);
            float pb01 = fmaxf(cmb.x, cmb.y), pb12 = fmaxf(cmb.y, cmb.z),
                  pb23 = fmaxf(cmb.z, cmb.w);
            float ha0 = fmaxf(la, pa01),   ha1 = fmaxf(pa01, cma.z);
            float ha2 = fmaxf(pa12, cma.w), ha3 = fmaxf(pa23, ra);
            float hb0 = fmaxf(lb, pb01),   hb1 = fmaxf(pb01, cmb.z);
            float hb2 = fmaxf(pb12, cmb.w), hb3 = fmaxf(pb23, rb);

            if (v1.x == ha0 && v1.x > best[0]) { best[0] = v1.x; bc[0] = c; }
            if (v1.y == ha1 && v1.y > best[1]) { best[1] = v1.y; bc[1] = c; }
            if (v1.z == ha2 && v1.z > best[2]) { best[2] = v1.z; bc[2] = c; }
            if (v1.w == ha3 && v1.w > best[3]) { best[3] = v1.w; bc[3] = c; }
            if (v2.x == hb0 && v2.x > best[4]) { best[4] = v2.x; bc[4] = c; }
            if (v2.y == hb1 && v2.y > best[5]) { best[5] = v2.y; bc[5] = c; }
            if (v2.z == hb2 && v2.z > best[6]) { best[6] = v2.z; bc[6] = c; }
            if (v2.w == hb3 && v2.w > best[7]) { best[7] = v2.w; bc[7] = c; }
        }

        __syncthreads();                        // all warps done reading slot
        if (c + DEPTH < NC) ISSUE(c + DEPTH, slot)
        asm volatile("cp.async.commit_group;"); // ALWAYS (possibly empty)

        slot = (slot + 1 == DEPTH) ? 0 : slot + 1;
    }
#undef ISSUE

    const int y0 = ybase + (warp << 1);
    const int x0 = lane << 2;
    const int o0 = (b << 14) + (y0 + 0) * WW + x0;
    const int o1 = (b << 14) + (y0 + 1) * WW + x0;
    float4 s0, s1;
    s0.x = best[0] > SCORE_THRESH ? best[0] : 0.f;
    s0.y = best[1] > SCORE_THRESH ? best[1] : 0.f;
    s0.z = best[2] > SCORE_THRESH ? best[2] : 0.f;
    s0.w = best[3] > SCORE_THRESH ? best[3] : 0.f;
    s1.x = best[4] > SCORE_THRESH ? best[4] : 0.f;
    s1.y = best[5] > SCORE_THRESH ? best[5] : 0.f;
    s1.z = best[6] > SCORE_THRESH ? best[6] : 0.f;
    s1.w = best[7] > SCORE_THRESH ? best[7] : 0.f;
    *(float4*)(g_conf + o0) = s0;
    *(float4*)(g_conf + o1) = s1;
    *(uchar4*)(g_cls + o0) = make_uchar4((unsigned char)bc[0], (unsigned char)bc[1],
                                         (unsigned char)bc[2], (unsigned char)bc[3]);
    *(uchar4*)(g_cls + o1) = make_uchar4((unsigned char)bc[4], (unsigned char)bc[5],
                                         (unsigned char)bc[6], (unsigned char)bc[7]);
}

// ---------------------------------------------------------------------------
// Kernel B: per-batch top-100. Early-stop ballot-count bisection (seeded at
// 0x3F7FF800 ~= 0.999878, expected to terminate in ~1 iteration on this
// distribution; exact on any data), multi-warp bitonic sort, gather, bitmask
// greedy per-class NMS, decode.
// ---------------------------------------------------------------------------
__global__ void __launch_bounds__(512) select_kernel(const float* __restrict__ wh,
                                                     const float* __restrict__ off,
                                                     float* __restrict__ out) {
    const int b = blockIdx.x;
    const int tid = threadIdx.x;
    const int wid = tid >> 5;
    const int lane = tid & 31;

    __shared__ int s_wcnt[16];
    __shared__ int s_tot;
    __shared__ unsigned long long s_cand[MAXCAND];
    __shared__ float s_x1[KTOP], s_y1[KTOP], s_x2[KTOP], s_y2[KTOP];
    __shared__ float s_area[KTOP], s_score[KTOP];
    __shared__ int s_cls[KTOP];
    __shared__ uint4 s_sup[KTOP];
    __shared__ unsigned int s_alive[4];
    __shared__ int s_n;

    // ---- load 32 score keys per thread into registers (coalesced) ----
    const float* cf = g_conf + (size_t)b * HWSZ;
    unsigned int key[32];
#pragma unroll
    for (int i = 0; i < 32; ++i)
        key[i] = __float_as_uint(cf[i * 512 + tid]);   // idx = i*512 + tid

    // ---- threshold by bisection with EARLY STOP: any T with
    // count(T) in [KTOP, MAXCAND] works (sort finishes the job).
    unsigned int lo = 1u, hi = 0x3F800000u;            // 1.0f strict upper bound
    unsigned int probe = 0x3F7FF800u;                  // seed ~0.999878
    unsigned int thr;
    while (true) {
        int c = 0;
#pragma unroll
        for (int i = 0; i < 32; ++i) c += (key[i] >= probe);
        c = __reduce_add_sync(0xffffffffu, c);
        if (lane == 0) s_wcnt[wid] = c;
        __syncthreads();
        if (wid == 0) {
            int t = (lane < 16) ? s_wcnt[lane] : 0;
            t = __reduce_add_sync(0xffffffffu, t);
            if (lane == 0) s_tot = t;
        }
        __syncthreads();
        int cnt = s_tot;
        if (cnt >= KTOP && cnt <= MAXCAND) { thr = probe; break; }
        if (cnt >= KTOP) lo = probe; else hi = probe;
        if (hi - lo <= 1u) { thr = lo; break; }
        probe = lo + ((hi - lo) >> 1);
    }

    // ---- compact candidates key >= thr, packed (key<<32)|~idx ----
    if (tid == 0) s_n = 0;
    __syncthreads();
#pragma unroll
    for (int i = 0; i < 32; ++i) {
        if (key[i] >= thr) {                 // thr >= 1 excludes zeros
            int p = atomicAdd(&s_n, 1);
            if (p < MAXCAND) {
                unsigned int idx = (unsigned int)(i * 512 + tid);
                s_cand[p] = ((unsigned long long)key[i] << 32) | (unsigned int)(~idx);
            }
        }
    }
    __syncthreads();
    int n = s_n < MAXCAND ? s_n : MAXCAND;
    for (int p = n + tid; p < MAXCAND; p += 512) s_cand[p] = 0ULL;
    __syncthreads();

    // ---- bitonic sort of 256 u64 descending; 1 element/thread across 8
    // warps: shfl_xor for j<32 (warps run in parallel), smem for j>=32.
    {
        unsigned long long v = (tid < MAXCAND) ? s_cand[tid] : 0ULL;
#pragma unroll
        for (int k = 2; k <= 256; k <<= 1) {
#pragma unroll
            for (int j = k >> 1; j > 0; j >>= 1) {
                bool desc = ((tid & k) == 0);
                bool low  = ((tid & j) == 0);
                bool keepMax = (desc == low);
                unsigned long long pv;
                if (j >= 32) {
                    __syncthreads();
                    if (tid < MAXCAND) s_cand[tid] = v;
                    __syncthreads();
                    pv = (tid < MAXCAND) ? s_cand[tid ^ j] : 0ULL;
                } else {
                    pv = __shfl_xor_sync(0xffffffffu, v, j);
                }
                unsigned long long mx = v > pv ? v : pv;
                unsigned long long mn = v > pv ? pv : v;
                v = keepMax ? mx : mn;
            }
        }
        __syncthreads();
        if (tid < MAXCAND) s_cand[tid] = v;
    }
    if (tid < 4) s_alive[tid] = 0u;
    if (tid < KTOP) s_sup[tid] = make_uint4(0u, 0u, 0u, 0u);
    __syncthreads();

    // ---- gather top-100, decode boxes (mirrors reference FP op order) ----
    if (tid < KTOP) {
        unsigned long long pk = s_cand[tid];
        unsigned int kk = (unsigned int)(pk >> 32);
        float score = __uint_as_float(kk);
        bool valid = score > SCORE_THRESH;
        float x1 = 0.f, y1 = 0.f, x2 = 0.f, y2 = 0.f;
        int cl = 0;
        if (valid) {
            unsigned int idx = ~((unsigned int)(pk & 0xffffffffu));
            int xi = idx & (WW - 1);
            int yi = idx >> 7;
            const float* whb = wh  + (size_t)b * 2 * HWSZ;
            const float* ofb = off + (size_t)b * 2 * HWSZ;
            float bw = whb[idx];
            float bh = whb[HWSZ + idx];
            float o0 = ofb[idx];
            float o1 = ofb[HWSZ + idx];
            float cx = (float)xi + o0;
            float cy = (float)yi + o1;
            const float invW = 1.0f / (float)WW;   // exact power of two
            const float invH = 1.0f / (float)HH;
            x1 = (cx - bw * 0.5f) * invW;
            y1 = (cy - bh * 0.5f) * invH;
            x2 = (cx + bw * 0.5f) * invW;
            y2 = (cy + bh * 0.5f) * invH;
            cl = (int)g_cls[(size_t)b * HWSZ + idx];
            atomicOr(&s_alive[tid >> 5], 1u << (tid & 31));
        }
        s_x1[tid] = x1; s_y1[tid] = y1; s_x2[tid] = x2; s_y2[tid] = y2;
        s_area[tid] = (x2 - x1) * (y2 - y1);
        s_score[tid] = score;
        s_cls[tid] = cl;
    }
    __syncthreads();

    // ---- parallel suppression-matrix build (bitmask rows) ----
    for (int idx = tid; idx < KTOP * KTOP; idx += 512) {
        int i = idx / KTOP;
        int jj = idx - i * KTOP;
        if (jj > i && s_cls[i] == s_cls[jj]) {
            float lx = fmaxf(s_x1[i], s_x1[jj]);
            float ly = fmaxf(s_y1[i], s_y1[jj]);
            float rx = fminf(s_x2[i], s_x2[jj]);
            float ry = fminf(s_y2[i], s_y2[jj]);
            float iw = fmaxf(rx - lx, 0.f);
            float ih = fmaxf(ry - ly, 0.f);
            float inter = iw * ih;
            float iou = inter / (s_area[i] + s_area[jj] - inter + 1e-9f);
            if (iou > NMS_THRESH)
                atomicOr(&((unsigned int*)s_sup)[i * 4 + (jj >> 5)], 1u << (jj & 31));
        }
    }
    __syncthreads();

    // ---- serial greedy sweep over bitmasks (thread 0, row prefetch) ----
    if (tid == 0) {
        unsigned int a0 = s_alive[0], a1 = s_alive[1], a2 = s_alive[2], a3 = s_alive[3];
        uint4 row = s_sup[0];
        for (int i = 0; i < KTOP; ++i) {
            uint4 nxt = (i + 1 < KTOP) ? s_sup[i + 1] : make_uint4(0u, 0u, 0u, 0u);
            unsigned int aw = (i < 32) ? a0 : (i < 64) ? a1 : (i < 96) ? a2 : a3;
            if ((aw >> (i & 31)) & 1u) {
                a0 &= ~row.x; a1 &= ~row.y; a2 &= ~row.z; a3 &= ~row.w;
            }
            row = nxt;
        }
        s_alive[0] = a0; s_alive[1] = a1; s_alive[2] = a2; s_alive[3] = a3;
    }
    __syncthreads();

    // ---- write dets (scale to image via the reference's recompute path) ----
    if (tid < KTOP) {
        bool alive = (s_alive[tid >> 5] >> (tid & 31)) & 1u;
        float* o = out + ((size_t)b * KTOP + tid) * 6;
        if (alive) {
            float x1 = s_x1[tid], y1 = s_y1[tid], x2 = s_x2[tid], y2 = s_y2[tid];
            float cxm = (x1 + x2) * 0.5f;
            float cym = (y1 + y2) * 0.5f;
            float cw = x2 - x1;
            float ch = y2 - y1;
            o[0] = (cxm - cw * 0.5f) * 512.f;
            o[1] = (cym - ch * 0.5f) * 512.f;
            o[2] = (cxm + cw * 0.5f) * 512.f;
            o[3] = (cym + ch * 0.5f) * 512.f;
            o[4] = s_score[tid];
            o[5] = (float)s_cls[tid];
        } else {
            o[0] = 0.f; o[1] = 0.f; o[2] = 0.f;
            o[3] = 0.f; o[4] = 0.f; o[5] = 0.f;
        }
    }
}

extern "C" void kernel_launch(void* const* d_in, const int* in_sizes, int n_in,
                              void* d_out, int out_size) {
    const float* hm  = (const float*)d_in[0];
    const float* wh  = (const float*)d_in[1];
    const float* off = (const float*)d_in[2];
    float* out = (float*)d_out;

    dim3 gA(HH / 16, NB);     // 8 x 32 = 256 blocks
    peak_kernel<<<gA, 256>>>(hm);
    select_kernel<<<NB, 512>>>(wh, off, out);
}

// round 16
// speedup vs baseline: 1.6735x; 1.3596x over previous
#include <cuda_runtime.h>
#include <float.h>
#include <stdint.h>

#define NB 32
#define NC 80
#define HH 128
#define WW 128
#define HWSZ 16384
#define KTOP 100
#define SCORE_THRESH 0.3f
#define NMS_THRESH 0.3f
#define MAXCAND 256

// scratch (device globals: allocation-free)
__device__ float g_conf[NB * HWSZ];          // thresholded scores
__device__ unsigned char g_cls[NB * HWSZ];   // argmax channel

__device__ __forceinline__ float4 neg4() {
    return make_float4(-FLT_MAX, -FLT_MAX, -FLT_MAX, -FLT_MAX);
}

// ---------------------------------------------------------------------------
// Kernel A: 3x3 peak-NMS + channel max/argmax.
// Warp owns 2 output rows x 128 cols (4 cols/lane, float4).
// 3-deep software pipeline over channels with 4 rotating register buffer
// sets (R10 structure, one buffer deeper): loads for channel c+3 issue while
// channel c is consumed, cutting the exposed DRAM latency per channel.
// ---------------------------------------------------------------------------
__global__ void __launch_bounds__(256, 2) peak_kernel(const float* __restrict__ hm) {
    const int b    = blockIdx.y;
    const int warp = threadIdx.x >> 5;
    const int lane = threadIdx.x & 31;
    const int y0   = (blockIdx.x << 4) + (warp << 1);   // output rows y0, y0+1
    const int x0   = lane << 2;

    const float* __restrict__ base = hm + (size_t)b * NC * HWSZ + x0;
    const bool topOK = (y0 > 0);
    const bool botOK = (y0 + 2 < HH);

    float best[8] = {0.f, 0.f, 0.f, 0.f, 0.f, 0.f, 0.f, 0.f};
    int   bc[8]   = {0, 0, 0, 0, 0, 0, 0, 0};

    float4 P0, P1, P2, P3, Q0, Q1, Q2, Q3, R0, R1, R2, R3, S0, S1, S2, S3;

#define LOADCH(T0, T1, T2, T3, cch)                                      \
    { const float* p_ = base + (size_t)(cch) * HWSZ;                     \
      T0 = topOK ? *(const float4*)(p_ + (y0 - 1) * WW) : neg4();        \
      T1 = *(const float4*)(p_ + (y0 + 0) * WW);                         \
      T2 = *(const float4*)(p_ + (y0 + 1) * WW);                         \
      T3 = botOK ? *(const float4*)(p_ + (y0 + 2) * WW) : neg4(); }

#define COMPUTE(T0, T1, T2, T3, cch)                                                  \
    { float4 t_, cma_, cmb_;                                                          \
      t_.x = fmaxf(T1.x, T2.x); t_.y = fmaxf(T1.y, T2.y);                             \
      t_.z = fmaxf(T1.z, T2.z); t_.w = fmaxf(T1.w, T2.w);                             \
      cma_.x = fmaxf(t_.x, T0.x); cma_.y = fmaxf(t_.y, T0.y);                         \
      cma_.z = fmaxf(t_.z, T0.z); cma_.w = fmaxf(t_.w, T0.w);                         \
      cmb_.x = fmaxf(t_.x, T3.x); cmb_.y = fmaxf(t_.y, T3.y);                         \
      cmb_.z = fmaxf(t_.z, T3.z); cmb_.w = fmaxf(t_.w, T3.w);                         \
      float la_ = __shfl_up_sync(0xffffffffu, cma_.w, 1);                             \
      float ra_ = __shfl_down_sync(0xffffffffu, cma_.x, 1);                           \
      float lb_ = __shfl_up_sync(0xffffffffu, cmb_.w, 1);                             \
      float rb_ = __shfl_down_sync(0xffffffffu, cmb_.x, 1);                           \
      if (lane == 0)  { la_ = -FLT_MAX; lb_ = -FLT_MAX; }                             \
      if (lane == 31) { ra_ = -FLT_MAX; rb_ = -FLT_MAX; }                             \
      float pa01 = fmaxf(cma_.x, cma_.y), pa12 = fmaxf(cma_.y, cma_.z),               \
            pa23 = fmaxf(cma_.z, cma_.w);                                             \
      float pb01 = fmaxf(cmb_.x, cmb_.y), pb12 = fmaxf(cmb_.y, cmb_.z),               \
            pb23 = fmaxf(cmb_.z, cmb_.w);                                             \
      float ha0 = fmaxf(la_, pa01),   ha1 = fmaxf(pa01, cma_.z);                      \
      float ha2 = fmaxf(pa12, cma_.w), ha3 = fmaxf(pa23, ra_);                        \
      float hb0 = fmaxf(lb_, pb01),   hb1 = fmaxf(pb01, cmb_.z);                      \
      float hb2 = fmaxf(pb12, cmb_.w), hb3 = fmaxf(pb23, rb_);                        \
      if (T1.x == ha0 && T1.x > best[0]) { best[0] = T1.x; bc[0] = (cch); }           \
      if (T1.y == ha1 && T1.y > best[1]) { best[1] = T1.y; bc[1] = (cch); }           \
      if (T1.z == ha2 && T1.z > best[2]) { best[2] = T1.z; bc[2] = (cch); }           \
      if (T1.w == ha3 && T1.w > best[3]) { best[3] = T1.w; bc[3] = (cch); }           \
      if (T2.x == hb0 && T2.x > best[4]) { best[4] = T2.x; bc[4] = (cch); }           \
      if (T2.y == hb1 && T2.y > best[5]) { best[5] = T2.y; bc[5] = (cch); }           \
      if (T2.z == hb2 && T2.z > best[6]) { best[6] = T2.z; bc[6] = (cch); }           \
      if (T2.w == hb3 && T2.w > best[7]) { best[7] = T2.w; bc[7] = (cch); } }

    LOADCH(P0, P1, P2, P3, 0)
    LOADCH(Q0, Q1, Q2, Q3, 1)
    LOADCH(R0, R1, R2, R3, 2)
#pragma unroll 1
    for (int c = 0; c + 6 < NC; c += 4) {     // 19 iters: c = 0..72
        LOADCH(S0, S1, S2, S3, c + 3)  COMPUTE(P0, P1, P2, P3, c)
        LOADCH(P0, P1, P2, P3, c + 4)  COMPUTE(Q0, Q1, Q2, Q3, c + 1)
        LOADCH(Q0, Q1, Q2, Q3, c + 5)  COMPUTE(R0, R1, R2, R3, c + 2)
        LOADCH(R0, R1, R2, R3, c + 6)  COMPUTE(S0, S1, S2, S3, c + 3)
    }
    // after loop: P = ch 76, Q = ch 77, R = ch 78
    LOADCH(S0, S1, S2, S3, NC - 1)
    COMPUTE(P0, P1, P2, P3, NC - 4)
    COMPUTE(Q0, Q1, Q2, Q3, NC - 3)
    COMPUTE(R0, R1, R2, R3, NC - 2)
    COMPUTE(S0, S1, S2, S3, NC - 1)
#undef LOADCH
#undef COMPUTE

    const int o0 = (b << 14) + (y0 + 0) * WW + x0;
    const int o1 = (b << 14) + (y0 + 1) * WW + x0;
    float4 s0, s1;
    s0.x = best[0] > SCORE_THRESH ? best[0] : 0.f;
    s0.y = best[1] > SCORE_THRESH ? best[1] : 0.f;
    s0.z = best[2] > SCORE_THRESH ? best[2] : 0.f;
    s0.w = best[3] > SCORE_THRESH ? best[3] : 0.f;
    s1.x = best[4] > SCORE_THRESH ? best[4] : 0.f;
    s1.y = best[5] > SCORE_THRESH ? best[5] : 0.f;
    s1.z = best[6] > SCORE_THRESH ? best[6] : 0.f;
    s1.w = best[7] > SCORE_THRESH ? best[7] : 0.f;
    *(float4*)(g_conf + o0) = s0;
    *(float4*)(g_conf + o1) = s1;
    *(uchar4*)(g_cls + o0) = make_uchar4((unsigned char)bc[0], (unsigned char)bc[1],
                                         (unsigned char)bc[2], (unsigned char)bc[3]);
    *(uchar4*)(g_cls + o1) = make_uchar4((unsigned char)bc[4], (unsigned char)bc[5],
                                         (unsigned char)bc[6], (unsigned char)bc[7]);
}

// ---------------------------------------------------------------------------
// Kernel B: per-batch top-100, 1024 threads (16 keys/thread). Early-stop
// ballot-count bisection (seeded), multi-warp bitonic sort, gather, bitmask
// greedy per-class NMS, decode.
// ---------------------------------------------------------------------------
__global__ void __launch_bounds__(1024) select_kernel(const float* __restrict__ wh,
                                                      const float* __restrict__ off,
                                                      float* __restrict__ out) {
    const int b = blockIdx.x;
    const int tid = threadIdx.x;
    const int wid = tid >> 5;
    const int lane = tid & 31;

    __shared__ int s_wcnt[32];
    __shared__ int s_tot;
    __shared__ unsigned long long s_cand[MAXCAND];
    __shared__ float s_x1[KTOP], s_y1[KTOP], s_x2[KTOP], s_y2[KTOP];
    __shared__ float s_area[KTOP], s_score[KTOP];
    __shared__ int s_cls[KTOP];
    __shared__ uint4 s_sup[KTOP];
    __shared__ unsigned int s_alive[4];
    __shared__ int s_n;

    // ---- load 16 score keys per thread into registers (coalesced) ----
    const float* cf = g_conf + (size_t)b * HWSZ;
    unsigned int key[16];
#pragma unroll
    for (int i = 0; i < 16; ++i)
        key[i] = __float_as_uint(cf[i * 1024 + tid]);   // idx = i*1024 + tid

    // ---- threshold by bisection with EARLY STOP: any T with
    // count(T) in [KTOP, MAXCAND] works (sort finishes the job).
    unsigned int lo = 1u, hi = 0x3F800000u;            // 1.0f strict upper bound
    unsigned int probe = 0x3F7FF800u;                  // seed ~0.999878
    unsigned int thr;
    while (true) {
        int c = 0;
#pragma unroll
        for (int i = 0; i < 16; ++i) c += (key[i] >= probe);
        c = __reduce_add_sync(0xffffffffu, c);
        if (lane == 0) s_wcnt[wid] = c;
        __syncthreads();
        if (wid == 0) {
            int t = s_wcnt[lane];
            t = __reduce_add_sync(0xffffffffu, t);
            if (lane == 0) s_tot = t;
        }
        __syncthreads();
        int cnt = s_tot;
        if (cnt >= KTOP && cnt <= MAXCAND) { thr = probe; break; }
        if (cnt >= KTOP) lo = probe; else hi = probe;
        if (hi - lo <= 1u) { thr = lo; break; }
        probe = lo + ((hi - lo) >> 1);
    }

    // ---- compact candidates key >= thr, packed (key<<32)|~idx ----
    if (tid == 0) s_n = 0;
    __syncthreads();
#pragma unroll
    for (int i = 0; i < 16; ++i) {
        if (key[i] >= thr) {                 // thr >= 1 excludes zeros
            int p = atomicAdd(&s_n, 1);
            if (p < MAXCAND) {
                unsigned int idx = (unsigned int)(i * 1024 + tid);
                s_cand[p] = ((unsigned long long)key[i] << 32) | (unsigned int)(~idx);
            }
        }
    }
    __syncthreads();
    int n = s_n < MAXCAND ? s_n : MAXCAND;
    for (int p = n + tid; p < MAXCAND; p += 1024) s_cand[p] = 0ULL;
    __syncthreads();

    // ---- bitonic sort of 256 u64 descending; 1 element/thread on the first
    // 8 warps: shfl_xor for j<32, smem for j>=32. All threads execute the
    // loop (barriers inside); threads >= 256 carry zeros.
    {
        unsigned long long v = (tid < MAXCAND) ? s_cand[tid] : 0ULL;
#pragma unroll
        for (int k = 2; k <= 256; k <<= 1) {
#pragma unroll
            for (int j = k >> 1; j > 0; j >>= 1) {
                bool desc = ((tid & k) == 0);
                bool low  = ((tid & j) == 0);
                bool keepMax = (desc == low);
                unsigned long long pv;
                if (j >= 32) {
                    __syncthreads();
                    if (tid < MAXCAND) s_cand[tid] = v;
                    __syncthreads();
                    pv = (tid < MAXCAND) ? s_cand[tid ^ j] : 0ULL;
                } else {
                    pv = __shfl_xor_sync(0xffffffffu, v, j);
                }
                unsigned long long mx = v > pv ? v : pv;
                unsigned long long mn = v > pv ? pv : v;
                v = keepMax ? mx : mn;
            }
        }
        __syncthreads();
        if (tid < MAXCAND) s_cand[tid] = v;
    }
    if (tid < 4) s_alive[tid] = 0u;
    if (tid < KTOP) s_sup[tid] = make_uint4(0u, 0u, 0u, 0u);
    __syncthreads();

    // ---- gather top-100, decode boxes (mirrors reference FP op order) ----
    if (tid < KTOP) {
        unsigned long long pk = s_cand[tid];
        unsigned int kk = (unsigned int)(pk >> 32);
        float score = __uint_as_float(kk);
        bool valid = score > SCORE_THRESH;
        float x1 = 0.f, y1 = 0.f, x2 = 0.f, y2 = 0.f;
        int cl = 0;
        if (valid) {
            unsigned int idx = ~((unsigned int)(pk & 0xffffffffu));
            int xi = idx & (WW - 1);
            int yi = idx >> 7;
            const float* whb = wh  + (size_t)b * 2 * HWSZ;
            const float* ofb = off + (size_t)b * 2 * HWSZ;
            float bw = whb[idx];
            float bh = whb[HWSZ + idx];
            float o0 = ofb[idx];
            float o1 = ofb[HWSZ + idx];
            float cx = (float)xi + o0;
            float cy = (float)yi + o1;
            const float invW = 1.0f / (float)WW;   // exact power of two
            const float invH = 1.0f / (float)HH;
            x1 = (cx - bw * 0.5f) * invW;
            y1 = (cy - bh * 0.5f) * invH;
            x2 = (cx + bw * 0.5f) * invW;
            y2 = (cy + bh * 0.5f) * invH;
            cl = (int)g_cls[(size_t)b * HWSZ + idx];
            atomicOr(&s_alive[tid >> 5], 1u << (tid & 31));
        }
        s_x1[tid] = x1; s_y1[tid] = y1; s_x2[tid] = x2; s_y2[tid] = y2;
        s_area[tid] = (x2 - x1) * (y2 - y1);
        s_score[tid] = score;
        s_cls[tid] = cl;
    }
    __syncthreads();

    // ---- parallel suppression-matrix build (bitmask rows) ----
    for (int idx = tid; idx < KTOP * KTOP; idx += 1024) {
        int i = idx / KTOP;
        int jj = idx - i * KTOP;
        if (jj > i && s_cls[i] == s_cls[jj]) {
            float lx = fmaxf(s_x1[i], s_x1[jj]);
            float ly = fmaxf(s_y1[i], s_y1[jj]);
            float rx = fminf(s_x2[i], s_x2[jj]);
            float ry = fminf(s_y2[i], s_y2[jj]);
            float iw = fmaxf(rx - lx, 0.f);
            float ih = fmaxf(ry - ly, 0.f);
            float inter = iw * ih;
            float iou = inter / (s_area[i] + s_area[jj] - inter + 1e-9f);
            if (iou > NMS_THRESH)
                atomicOr(&((unsigned int*)s_sup)[i * 4 + (jj >> 5)], 1u << (jj & 31));
        }
    }
    __syncthreads();

    // ---- serial greedy sweep over bitmasks (thread 0, row prefetch) ----
    if (tid == 0) {
        unsigned int a0 = s_alive[0], a1 = s_alive[1], a2 = s_alive[2], a3 = s_alive[3];
        uint4 row = s_sup[0];
        for (int i = 0; i < KTOP; ++i) {
            uint4 nxt = (i + 1 < KTOP) ? s_sup[i + 1] : make_uint4(0u, 0u, 0u, 0u);
            unsigned int aw = (i < 32) ? a0 : (i < 64) ? a1 : (i < 96) ? a2 : a3;
            if ((aw >> (i & 31)) & 1u) {
                a0 &= ~row.x; a1 &= ~row.y; a2 &= ~row.z; a3 &= ~row.w;
            }
            row = nxt;
        }
        s_alive[0] = a0; s_alive[1] = a1; s_alive[2] = a2; s_alive[3] = a3;
    }
    __syncthreads();

    // ---- write dets (scale to image via the reference's recompute path) ----
    if (tid < KTOP) {
        bool alive = (s_alive[tid >> 5] >> (tid & 31)) & 1u;
        float* o = out + ((size_t)b * KTOP + tid) * 6;
        if (alive) {
            float x1 = s_x1[tid], y1 = s_y1[tid], x2 = s_x2[tid], y2 = s_y2[tid];
            float cxm = (x1 + x2) * 0.5f;
            float cym = (y1 + y2) * 0.5f;
            float cw = x2 - x1;
            float ch = y2 - y1;
            o[0] = (cxm - cw * 0.5f) * 512.f;
            o[1] = (cym - ch * 0.5f) * 512.f;
            o[2] = (cxm + cw * 0.5f) * 512.f;
            o[3] = (cym + ch * 0.5f) * 512.f;
            o[4] = s_score[tid];
            o[5] = (float)s_cls[tid];
        } else {
            o[0] = 0.f; o[1] = 0.f; o[2] = 0.f;
            o[3] = 0.f; o[4] = 0.f; o[5] = 0.f;
        }
    }
}

extern "C" void kernel_launch(void* const* d_in, const int* in_sizes, int n_in,
                              void* d_out, int out_size) {
    const float* hm  = (const float*)d_in[0];
    const float* wh  = (const float*)d_in[1];
    const float* off = (const float*)d_in[2];
    float* out = (float*)d_out;

    dim3 gA(HH / 16, NB);     // 8 x 32 = 256 blocks
    peak_kernel<<<gA, 256>>>(hm);
    select_kernel<<<NB, 1024>>>(wh, off, out);
}

// round 17
// speedup vs baseline: 1.6746x; 1.0007x over previous
#include <cuda_runtime.h>
#include <float.h>
#include <stdint.h>

#define NB 32
#define NC 80
#define HH 128
#define WW 128
#define HWSZ 16384
#define KTOP 100
#define SCORE_THRESH 0.3f
#define NMS_THRESH 0.3f
#define MAXCAND 256

// scratch (device globals: allocation-free)
__device__ float g_conf[NB * HWSZ];          // thresholded scores
__device__ unsigned char g_cls[NB * HWSZ];   // argmax channel

__device__ __forceinline__ float4 neg4() {
    return make_float4(-FLT_MAX, -FLT_MAX, -FLT_MAX, -FLT_MAX);
}

// ---------------------------------------------------------------------------
// Kernel A: 3x3 peak-NMS + channel max/argmax.
// Warp owns 2 output rows x 128 cols (4 cols/lane, float4).
// 4-deep software pipeline over channels with 5 rotating register buffer
// sets: loads for channel c+4 issue while channel c is consumed.
// ---------------------------------------------------------------------------
__global__ void __launch_bounds__(256, 2) peak_kernel(const float* __restrict__ hm) {
    const int b    = blockIdx.y;
    const int warp = threadIdx.x >> 5;
    const int lane = threadIdx.x & 31;
    const int y0   = (blockIdx.x << 4) + (warp << 1);   // output rows y0, y0+1
    const int x0   = lane << 2;

    const float* __restrict__ base = hm + (size_t)b * NC * HWSZ + x0;
    const bool topOK = (y0 > 0);
    const bool botOK = (y0 + 2 < HH);

    float best[8] = {0.f, 0.f, 0.f, 0.f, 0.f, 0.f, 0.f, 0.f};
    int   bc[8]   = {0, 0, 0, 0, 0, 0, 0, 0};

    float4 P0, P1, P2, P3, Q0, Q1, Q2, Q3, R0, R1, R2, R3,
           S0, S1, S2, S3, T0, T1, T2, T3;

#define LOADCH(U0, U1, U2, U3, cch)                                      \
    { const float* p_ = base + (size_t)(cch) * HWSZ;                     \
      U0 = topOK ? *(const float4*)(p_ + (y0 - 1) * WW) : neg4();        \
      U1 = *(const float4*)(p_ + (y0 + 0) * WW);                         \
      U2 = *(const float4*)(p_ + (y0 + 1) * WW);                         \
      U3 = botOK ? *(const float4*)(p_ + (y0 + 2) * WW) : neg4(); }

#define COMPUTE(U0, U1, U2, U3, cch)                                                  \
    { float4 t_, cma_, cmb_;                                                          \
      t_.x = fmaxf(U1.x, U2.x); t_.y = fmaxf(U1.y, U2.y);                             \
      t_.z = fmaxf(U1.z, U2.z); t_.w = fmaxf(U1.w, U2.w);                             \
      cma_.x = fmaxf(t_.x, U0.x); cma_.y = fmaxf(t_.y, U0.y);                         \
      cma_.z = fmaxf(t_.z, U0.z); cma_.w = fmaxf(t_.w, U0.w);                         \
      cmb_.x = fmaxf(t_.x, U3.x); cmb_.y = fmaxf(t_.y, U3.y);                         \
      cmb_.z = fmaxf(t_.z, U3.z); cmb_.w = fmaxf(t_.w, U3.w);                         \
      float la_ = __shfl_up_sync(0xffffffffu, cma_.w, 1);                             \
      float ra_ = __shfl_down_sync(0xffffffffu, cma_.x, 1);                           \
      float lb_ = __shfl_up_sync(0xffffffffu, cmb_.w, 1);                             \
      float rb_ = __shfl_down_sync(0xffffffffu, cmb_.x, 1);                           \
      if (lane == 0)  { la_ = -FLT_MAX; lb_ = -FLT_MAX; }                             \
      if (lane == 31) { ra_ = -FLT_MAX; rb_ = -FLT_MAX; }                             \
      float pa01 = fmaxf(cma_.x, cma_.y), pa12 = fmaxf(cma_.y, cma_.z),               \
            pa23 = fmaxf(cma_.z, cma_.w);                                             \
      float pb01 = fmaxf(cmb_.x, cmb_.y), pb12 = fmaxf(cmb_.y, cmb_.z),               \
            pb23 = fmaxf(cmb_.z, cmb_.w);                                             \
      float ha0 = fmaxf(la_, pa01),   ha1 = fmaxf(pa01, cma_.z);                      \
      float ha2 = fmaxf(pa12, cma_.w), ha3 = fmaxf(pa23, ra_);                        \
      float hb0 = fmaxf(lb_, pb01),   hb1 = fmaxf(pb01, cmb_.z);                      \
      float hb2 = fmaxf(pb12, cmb_.w), hb3 = fmaxf(pb23, rb_);                        \
      if (U1.x == ha0 && U1.x > best[0]) { best[0] = U1.x; bc[0] = (cch); }           \
      if (U1.y == ha1 && U1.y > best[1]) { best[1] = U1.y; bc[1] = (cch); }           \
      if (U1.z == ha2 && U1.z > best[2]) { best[2] = U1.z; bc[2] = (cch); }           \
      if (U1.w == ha3 && U1.w > best[3]) { best[3] = U1.w; bc[3] = (cch); }           \
      if (U2.x == hb0 && U2.x > best[4]) { best[4] = U2.x; bc[4] = (cch); }           \
      if (U2.y == hb1 && U2.y > best[5]) { best[5] = U2.y; bc[5] = (cch); }           \
      if (U2.z == hb2 && U2.z > best[6]) { best[6] = U2.z; bc[6] = (cch); }           \
      if (U2.w == hb3 && U2.w > best[7]) { best[7] = U2.w; bc[7] = (cch); } }

    LOADCH(P0, P1, P2, P3, 0)
    LOADCH(Q0, Q1, Q2, Q3, 1)
    LOADCH(R0, R1, R2, R3, 2)
    LOADCH(S0, S1, S2, S3, 3)
#pragma unroll 1
    for (int c = 0; c + 8 < NC; c += 5) {     // 15 iters: c = 0..70
        LOADCH(T0, T1, T2, T3, c + 4)  COMPUTE(P0, P1, P2, P3, c)
        LOADCH(P0, P1, P2, P3, c + 5)  COMPUTE(Q0, Q1, Q2, Q3, c + 1)
        LOADCH(Q0, Q1, Q2, Q3, c + 6)  COMPUTE(R0, R1, R2, R3, c + 2)
        LOADCH(R0, R1, R2, R3, c + 7)  COMPUTE(S0, S1, S2, S3, c + 3)
        LOADCH(S0, S1, S2, S3, c + 8)  COMPUTE(T0, T1, T2, T3, c + 4)
    }
    // after loop: P = ch 75, Q = ch 76, R = ch 77, S = ch 78
    LOADCH(T0, T1, T2, T3, NC - 1)
    COMPUTE(P0, P1, P2, P3, NC - 5)
    COMPUTE(Q0, Q1, Q2, Q3, NC - 4)
    COMPUTE(R0, R1, R2, R3, NC - 3)
    COMPUTE(S0, S1, S2, S3, NC - 2)
    COMPUTE(T0, T1, T2, T3, NC - 1)
#undef LOADCH
#undef COMPUTE

    const int o0 = (b << 14) + (y0 + 0) * WW + x0;
    const int o1 = (b << 14) + (y0 + 1) * WW + x0;
    float4 s0, s1;
    s0.x = best[0] > SCORE_THRESH ? best[0] : 0.f;
    s0.y = best[1] > SCORE_THRESH ? best[1] : 0.f;
    s0.z = best[2] > SCORE_THRESH ? best[2] : 0.f;
    s0.w = best[3] > SCORE_THRESH ? best[3] : 0.f;
    s1.x = best[4] > SCORE_THRESH ? best[4] : 0.f;
    s1.y = best[5] > SCORE_THRESH ? best[5] : 0.f;
    s1.z = best[6] > SCORE_THRESH ? best[6] : 0.f;
    s1.w = best[7] > SCORE_THRESH ? best[7] : 0.f;
    *(float4*)(g_conf + o0) = s0;
    *(float4*)(g_conf + o1) = s1;
    *(uchar4*)(g_cls + o0) = make_uchar4((unsigned char)bc[0], (unsigned char)bc[1],
                                         (unsigned char)bc[2], (unsigned char)bc[3]);
    *(uchar4*)(g_cls + o1) = make_uchar4((unsigned char)bc[4], (unsigned char)bc[5],
                                         (unsigned char)bc[6], (unsigned char)bc[7]);
}

// ---------------------------------------------------------------------------
// Kernel B: per-batch top-100, 1024 threads (16 keys/thread). Early-stop
// ballot-count bisection (seeded), multi-warp bitonic sort (shuffle phase
// restricted to the 8 data-carrying warps), gather, bitmask greedy per-class
// NMS, decode.
// ---------------------------------------------------------------------------
__global__ void __launch_bounds__(1024) select_kernel(const float* __restrict__ wh,
                                                      const float* __restrict__ off,
                                                      float* __restrict__ out) {
    const int b = blockIdx.x;
    const int tid = threadIdx.x;
    const int wid = tid >> 5;
    const int lane = tid & 31;

    __shared__ int s_wcnt[32];
    __shared__ int s_tot;
    __shared__ unsigned long long s_cand[MAXCAND];
    __shared__ float s_x1[KTOP], s_y1[KTOP], s_x2[KTOP], s_y2[KTOP];
    __shared__ float s_area[KTOP], s_score[KTOP];
    __shared__ int s_cls[KTOP];
    __shared__ uint4 s_sup[KTOP];
    __shared__ unsigned int s_alive[4];
    __shared__ int s_n;

    // ---- load 16 score keys per thread into registers (coalesced) ----
    const float* cf = g_conf + (size_t)b * HWSZ;
    unsigned int key[16];
#pragma unroll
    for (int i = 0; i < 16; ++i)
        key[i] = __float_as_uint(__ldg(cf + i * 1024 + tid));  // idx = i*1024+tid

    // ---- threshold by bisection with EARLY STOP: any T with
    // count(T) in [KTOP, MAXCAND] works (sort finishes the job).
    unsigned int lo = 1u, hi = 0x3F800000u;            // 1.0f strict upper bound
    unsigned int probe = 0x3F7FF800u;                  // seed ~0.999878
    unsigned int thr;
    while (true) {
        int c = 0;
#pragma unroll
        for (int i = 0; i < 16; ++i) c += (key[i] >= probe);
        c = __reduce_add_sync(0xffffffffu, c);
        if (lane == 0) s_wcnt[wid] = c;
        __syncthreads();
        if (wid == 0) {
            int t = s_wcnt[lane];
            t = __reduce_add_sync(0xffffffffu, t);
            if (lane == 0) s_tot = t;
        }
        __syncthreads();
        int cnt = s_tot;
        if (cnt >= KTOP && cnt <= MAXCAND) { thr = probe; break; }
        if (cnt >= KTOP) lo = probe; else hi = probe;
        if (hi - lo <= 1u) { thr = lo; break; }
        probe = lo + ((hi - lo) >> 1);
    }

    // ---- compact candidates key >= thr, packed (key<<32)|~idx ----
    if (tid == 0) s_n = 0;
    __syncthreads();
#pragma unroll
    for (int i = 0; i < 16; ++i) {
        if (key[i] >= thr) {                 // thr >= 1 excludes zeros
            int p = atomicAdd(&s_n, 1);
            if (p < MAXCAND) {
                unsigned int idx = (unsigned int)(i * 1024 + tid);
                s_cand[p] = ((unsigned long long)key[i] << 32) | (unsigned int)(~idx);
            }
        }
    }
    __syncthreads();
    int n = s_n < MAXCAND ? s_n : MAXCAND;
    for (int p = n + tid; p < MAXCAND; p += 1024) s_cand[p] = 0ULL;
    __syncthreads();

    // ---- bitonic sort of 256 u64 descending; 1 element/thread on the first
    // 8 warps. Shuffle phase (j<32) runs ONLY on those warps; smem phases
    // keep unconditional barriers.
    {
        unsigned long long v = (tid < MAXCAND) ? s_cand[tid] : 0ULL;
#pragma unroll
        for (int k = 2; k <= 256; k <<= 1) {
#pragma unroll
            for (int j = k >> 1; j > 0; j >>= 1) {
                if (j >= 32) {
                    __syncthreads();
                    if (tid < MAXCAND) s_cand[tid] = v;
                    __syncthreads();
                    if (tid < MAXCAND) {
                        unsigned long long pv = s_cand[tid ^ j];
                        bool keepMax = (((tid & k) == 0) == ((tid & j) == 0));
                        unsigned long long mx = v > pv ? v : pv;
                        unsigned long long mn = v > pv ? pv : v;
                        v = keepMax ? mx : mn;
                    }
                } else if (tid < MAXCAND) {
                    unsigned long long pv = __shfl_xor_sync(0xffffffffu, v, j);
                    bool keepMax = (((tid & k) == 0) == ((tid & j) == 0));
                    unsigned long long mx = v > pv ? v : pv;
                    unsigned long long mn = v > pv ? pv : v;
                    v = keepMax ? mx : mn;
                }
            }
        }
        __syncthreads();
        if (tid < MAXCAND) s_cand[tid] = v;
    }
    if (tid < 4) s_alive[tid] = 0u;
    if (tid < KTOP) s_sup[tid] = make_uint4(0u, 0u, 0u, 0u);
    __syncthreads();

    // ---- gather top-100, decode boxes (mirrors reference FP op order) ----
    if (tid < KTOP) {
        unsigned long long pk = s_cand[tid];
        unsigned int kk = (unsigned int)(pk >> 32);
        float score = __uint_as_float(kk);
        bool valid = score > SCORE_THRESH;
        float x1 = 0.f, y1 = 0.f, x2 = 0.f, y2 = 0.f;
        int cl = 0;
        if (valid) {
            unsigned int idx = ~((unsigned int)(pk & 0xffffffffu));
            int xi = idx & (WW - 1);
            int yi = idx >> 7;
            const float* whb = wh  + (size_t)b * 2 * HWSZ;
            const float* ofb = off + (size_t)b * 2 * HWSZ;
            float bw = whb[idx];
            float bh = whb[HWSZ + idx];
            float o0 = ofb[idx];
            float o1 = ofb[HWSZ + idx];
            float cx = (float)xi + o0;
            float cy = (float)yi + o1;
            const float invW = 1.0f / (float)WW;   // exact power of two
            const float invH = 1.0f / (float)HH;
            x1 = (cx - bw * 0.5f) * invW;
            y1 = (cy - bh * 0.5f) * invH;
            x2 = (cx + bw * 0.5f) * invW;
            y2 = (cy + bh * 0.5f) * invH;
            cl = (int)g_cls[(size_t)b * HWSZ + idx];
            atomicOr(&s_alive[tid >> 5], 1u << (tid & 31));
        }
        s_x1[tid] = x1; s_y1[tid] = y1; s_x2[tid] = x2; s_y2[tid] = y2;
        s_area[tid] = (x2 - x1) * (y2 - y1);
        s_score[tid] = score;
        s_cls[tid] = cl;
    }
    __syncthreads();

    // ---- parallel suppression-matrix build (bitmask rows) ----
    for (int idx = tid; idx < KTOP * KTOP; idx += 1024) {
        int i = idx / KTOP;
        int jj = idx - i * KTOP;
        if (jj > i && s_cls[i] == s_cls[jj]) {
            float lx = fmaxf(s_x1[i], s_x1[jj]);
            float ly = fmaxf(s_y1[i], s_y1[jj]);
            float rx = fminf(s_x2[i], s_x2[jj]);
            float ry = fminf(s_y2[i], s_y2[jj]);
            float iw = fmaxf(rx - lx, 0.f);
            float ih = fmaxf(ry - ly, 0.f);
            float inter = iw * ih;
            float iou = inter / (s_area[i] + s_area[jj] - inter + 1e-9f);
            if (iou > NMS_THRESH)
                atomicOr(&((unsigned int*)s_sup)[i * 4 + (jj >> 5)], 1u << (jj & 31));
        }
    }
    __syncthreads();

    // ---- serial greedy sweep over bitmasks (thread 0, row prefetch) ----
    if (tid == 0) {
        unsigned int a0 = s_alive[0], a1 = s_alive[1], a2 = s_alive[2], a3 = s_alive[3];
        uint4 row = s_sup[0];
        for (int i = 0; i < KTOP; ++i) {
            uint4 nxt = (i + 1 < KTOP) ? s_sup[i + 1] : make_uint4(0u, 0u, 0u, 0u);
            unsigned int aw = (i < 32) ? a0 : (i < 64) ? a1 : (i < 96) ? a2 : a3;
            if ((aw >> (i & 31)) & 1u) {
                a0 &= ~row.x; a1 &= ~row.y; a2 &= ~row.z; a3 &= ~row.w;
            }
            row = nxt;
        }
        s_alive[0] = a0; s_alive[1] = a1; s_alive[2] = a2; s_alive[3] = a3;
    }
    __syncthreads();

    // ---- write dets (scale to image via the reference's recompute path) ----
    if (tid < KTOP) {
        bool alive = (s_alive[tid >> 5] >> (tid & 31)) & 1u;
        float* o = out + ((size_t)b * KTOP + tid) * 6;
        if (alive) {
            float x1 = s_x1[tid], y1 = s_y1[tid], x2 = s_x2[tid], y2 = s_y2[tid];
            float cxm = (x1 + x2) * 0.5f;
            float cym = (y1 + y2) * 0.5f;
            float cw = x2 - x1;
            float ch = y2 - y1;
            o[0] = (cxm - cw * 0.5f) * 512.f;
            o[1] = (cym - ch * 0.5f) * 512.f;
            o[2] = (cxm + cw * 0.5f) * 512.f;
            o[3] = (cym + ch * 0.5f) * 512.f;
            o[4] = s_score[tid];
            o[5] = (float)s_cls[tid];
        } else {
            o[0] = 0.f; o[1] = 0.f; o[2] = 0.f;
            o[3] = 0.f; o[4] = 0.f; o[5] = 0.f;
        }
    }
}

extern "C" void kernel_launch(void* const* d_in, const int* in_sizes, int n_in,
                              void* d_out, int out_size) {
    const float* hm  = (const float*)d_in[0];
    const float* wh  = (const float*)d_in[1];
    const float* off = (const float*)d_in[2];
    float* out = (float*)d_out;

    dim3 gA(HH / 16, NB);     // 8 x 32 = 256 blocks
    peak_kernel<<<gA, 256>>>(hm);
    select_kernel<<<NB, 1024>>>(wh, off, out);
}